// round 17
// baseline (speedup 1.0000x reference)
#include <cuda_runtime.h>
#include <cuda.h>
#include <cuda_fp16.h>
#include <cstdint>
#include <cstdio>
#include <cstring>

// ---------------- problem constants ----------------
#define B_   32
#define C_   512
#define H_   32
#define W_   32
#define NH_  16
#define WS_  4
#define HD_  32
#define NTOK 16
#define T_   32768
#define MLPH 2048
#define EPS_ 1e-5f

// ---------------- scratch (device globals; no allocs allowed) ----------------
__device__ __half g_xh_h [ (size_t)T_ * C_ ];
__device__ __half g_xh2_h[ (size_t)T_ * C_ ];
__device__ __half g_qkv_h[ (size_t)T_ * 3 * C_ ];
__device__ __half g_xn_h [ (size_t)T_ * C_ ];
__device__ __half g_ctx_h[ (size_t)T_ * C_ ];
__device__ __half g_hn_h [ (size_t)T_ * C_ ];
__device__ __half g_h1_h [ (size_t)T_ * MLPH ];
__device__ __half g_wq_h [ (size_t)3 * C_ * C_ ];
__device__ __half g_wp_h [ (size_t)C_ * C_ ];
__device__ __half g_w1_h [ (size_t)MLPH * C_ ];
__device__ __half g_w2_h [ (size_t)C_ * MLPH ];

// ---------------- mma / ldmatrix ----------------
__device__ __forceinline__ void mma_f16(float* c, const uint32_t* a, const uint32_t* b) {
    asm volatile("mma.sync.aligned.m16n8k16.row.col.f32.f16.f16.f32 "
        "{%0,%1,%2,%3}, {%4,%5,%6,%7}, {%8,%9}, {%0,%1,%2,%3};\n"
        : "+f"(c[0]), "+f"(c[1]), "+f"(c[2]), "+f"(c[3])
        : "r"(a[0]), "r"(a[1]), "r"(a[2]), "r"(a[3]),
          "r"(b[0]), "r"(b[1]));
}

#define LDMX4(r, addr) \
    asm volatile("ldmatrix.sync.aligned.m8n8.x4.shared.b16 {%0,%1,%2,%3}, [%4];" \
        : "=r"((r)[0]), "=r"((r)[1]), "=r"((r)[2]), "=r"((r)[3]) : "r"(addr))

#define LDMX4T(r, addr) \
    asm volatile("ldmatrix.sync.aligned.m8n8.x4.trans.shared.b16 {%0,%1,%2,%3}, [%4];" \
        : "=r"((r)[0]), "=r"((r)[1]), "=r"((r)[2]), "=r"((r)[3]) : "r"(addr))

__device__ __forceinline__ uint32_t h2u(__half2 h) {
    uint32_t u;
    memcpy(&u, &h, 4);
    return u;
}

// ---------------- cp.async (attention staging) ----------------
__device__ __forceinline__ void cp16(const void* sdst, const void* gsrc) {
    uint32_t s = (uint32_t)__cvta_generic_to_shared(sdst);
    asm volatile("cp.async.cg.shared.global [%0], [%1], 16;\n" :: "r"(s), "l"(gsrc));
}
#define CP_COMMIT() asm volatile("cp.async.commit_group;\n" ::: "memory")
#define CP_WAIT0()  asm volatile("cp.async.wait_group 0;\n" ::: "memory")
#define CP_WAIT1()  asm volatile("cp.async.wait_group 1;\n" ::: "memory")

// ---------------- TMA / mbarrier ----------------
#define MBARRIER_INIT(mbar, count) \
    asm volatile("mbarrier.init.shared.b64 [%0], %1;" \
        :: "r"((uint32_t)(mbar)), "r"((uint32_t)(count)) : "memory")
#define MBARRIER_EXPECT_TX(mbar, bytes) \
    asm volatile("mbarrier.arrive.expect_tx.shared.b64 _, [%0], %1;" \
        :: "r"((uint32_t)(mbar)), "r"((uint32_t)(bytes)) : "memory")

#define MBARRIER_WAIT_PARITY(mbar, parity) do { \
    uint32_t _m = (uint32_t)(mbar), _p = (uint32_t)(parity), _d; \
    asm volatile("{\n\t.reg .pred p;\n\t" \
        "mbarrier.try_wait.parity.acquire.cta.shared::cta.b64 p, [%1], %2;\n\t" \
        "selp.b32 %0, 1, 0, p;\n\t}" : "=r"(_d) : "r"(_m), "r"(_p) : "memory"); \
    if (!_d) { \
        asm volatile("{\n\t.reg .pred P1;\n\t" \
            "WAIT_LOOP_%=:\n\t" \
            "mbarrier.try_wait.parity.acquire.cta.shared::cta.b64 P1, [%0], %1, 0x989680;\n\t" \
            "@P1 bra.uni WAIT_DONE_%=;\n\t" \
            "bra.uni WAIT_LOOP_%=;\n\t" \
            "WAIT_DONE_%=:\n\t}" :: "r"(_m), "r"(_p) : "memory"); \
    } \
} while (0)

#define TMA2D(saddr, tmap, cx, cy, mbar) \
    asm volatile("cp.async.bulk.tensor.2d.shared::cta.global.tile.mbarrier::complete_tx::bytes " \
        "[%0], [%1, {%2, %3}], [%4];" \
        :: "r"((uint32_t)(saddr)), "l"(tmap), "r"((int32_t)(cx)), "r"((int32_t)(cy)), \
           "r"((uint32_t)(mbar)) : "memory")

__device__ __forceinline__ float gelu_exact(float x) {
    return 0.5f * x * (1.0f + erff(x * 0.7071067811865475f));
}

// ===================================================================
// single fused fp32 -> fp16 conversion of all 4 weight matrices
// ===================================================================
#define NQ (3 * C_ * C_)
#define NP (C_ * C_)
#define N1 (MLPH * C_)
#define N2 (C_ * MLPH)
__global__ void f2h_all_kernel(const float* __restrict__ wq, const float* __restrict__ wp,
                               const float* __restrict__ w1, const float* __restrict__ w2,
                               __half* __restrict__ dq, __half* __restrict__ dp,
                               __half* __restrict__ d1, __half* __restrict__ d2) {
    int i = (blockIdx.x * blockDim.x + threadIdx.x) * 4;
    const float* s; __half* d; int off;
    if (i < NQ)                     { s = wq; d = dq; off = i; }
    else if (i < NQ + NP)           { s = wp; d = dp; off = i - NQ; }
    else if (i < NQ + NP + N1)      { s = w1; d = d1; off = i - NQ - NP; }
    else if (i < NQ + NP + N1 + N2) { s = w2; d = d2; off = i - NQ - NP - N1; }
    else return;
    float4 v = *(const float4*)(s + off);
    __half2* dpp = (__half2*)(d + off);
    dpp[0] = __floats2half2_rn(v.x, v.y);
    dpp[1] = __floats2half2_rn(v.z, v.w);
}

// ===================================================================
// fp16 GEMM (unchanged): 2-stage TMA ring, 3 CTAs/SM
// ===================================================================
#define STAGE_B  32768
#define MB_OFF   (2 * STAGE_B)
#define GSMEM    (MB_OFF + 128)

template<int MODE>
__global__ void __launch_bounds__(128, 3) gemm_h(
    const __grid_constant__ CUtensorMap tmA,
    const __grid_constant__ CUtensorMap tmB,
    const float* __restrict__ bias, const void* __restrict__ resv,
    void* __restrict__ outv, int N, int K)
{
    extern __shared__ __align__(1024) char smem[];
    const uint32_t sbase = (uint32_t)__cvta_generic_to_shared(smem);
    const uint32_t mb = sbase + MB_OFF;

    const int tid  = threadIdx.x;
    const int lane = tid & 31, warp = tid >> 5;
    const int bm   = blockIdx.y * 128;
    const int bn   = blockIdx.x * 128;
    const int wm   = (warp & 1) * 64;
    const int wn   = (warp >> 1) * 64;
    const int tq   = lane & 3, g = lane >> 2;
    const int nK   = K >> 6;

    const int lsub = lane & 7;
    const int lh   = (lane >> 3) & 1;
    const int lk   = lane >> 4;
    const uint32_t rowoff = (uint32_t)((lh * 8 + lsub) * 128);

    if (tid == 0) {
        MBARRIER_INIT(mb,     1);
        MBARRIER_INIT(mb + 8, 1);
    }
    __syncthreads();

    float acc[4][8][4];
    #pragma unroll
    for (int i = 0; i < 4; ++i)
        #pragma unroll
        for (int j = 0; j < 8; ++j)
            #pragma unroll
            for (int e = 0; e < 4; ++e) acc[i][j][e] = 0.f;

    if (tid == 0) {
        MBARRIER_EXPECT_TX(mb, STAGE_B);
        TMA2D(sbase,         &tmA, 0, bm, mb);
        TMA2D(sbase + 16384, &tmB, 0, bn, mb);
    }

    for (int kt = 0; kt < nK; ++kt) {
        const int st = kt & 1;
        MBARRIER_WAIT_PARITY(mb + 8 * st, (kt >> 1) & 1);
        __syncthreads();

        if (tid == 0) {
            int kn = kt + 1;
            if (kn < nK) {
                int sn = kn & 1;
                MBARRIER_EXPECT_TX(mb + 8 * sn, STAGE_B);
                TMA2D(sbase + sn * STAGE_B,         &tmA, kn * 64, bm, mb + 8 * sn);
                TMA2D(sbase + sn * STAGE_B + 16384, &tmB, kn * 64, bn, mb + 8 * sn);
            }
        }

        const uint32_t As = sbase + st * STAGE_B;
        const uint32_t Bs = As + 16384;

        #pragma unroll
        for (int j = 0; j < 4; ++j) {
            const uint32_t ck = (uint32_t)((((2 * j) + lk) ^ lsub) * 16);
            uint32_t a[4][4], bb[4][4];
            #pragma unroll
            for (int mi = 0; mi < 4; ++mi)
                LDMX4(a[mi], As + (uint32_t)((wm + mi * 16) * 128) + rowoff + ck);
            #pragma unroll
            for (int np = 0; np < 4; ++np)
                LDMX4(bb[np], Bs + (uint32_t)((wn + np * 16) * 128) + rowoff + ck);
            #pragma unroll
            for (int mi = 0; mi < 4; ++mi) {
                #pragma unroll
                for (int np = 0; np < 4; ++np) {
                    uint32_t b0[2] = { bb[np][0], bb[np][2] };
                    uint32_t b1[2] = { bb[np][1], bb[np][3] };
                    mma_f16(acc[mi][2 * np],     a[mi], b0);
                    mma_f16(acc[mi][2 * np + 1], a[mi], b1);
                }
            }
        }
    }

    #pragma unroll
    for (int mi = 0; mi < 4; ++mi) {
        #pragma unroll
        for (int ni = 0; ni < 8; ++ni) {
            int c = bn + wn + ni * 8 + tq * 2;
            float2 bv = *(const float2*)(bias + c);
            #pragma unroll
            for (int half = 0; half < 2; ++half) {
                int r = bm + wm + mi * 16 + g + half * 8;
                float v0 = acc[mi][ni][half * 2 + 0] + bv.x;
                float v1 = acc[mi][ni][half * 2 + 1] + bv.y;
                if (MODE == 1) {
                    *(__half2*)((__half*)outv + (size_t)r * N + c) =
                        __floats2half2_rn(gelu_exact(v0), gelu_exact(v1));
                } else if (MODE == 2) {
                    float2 rf = __half22float2(
                        *(const __half2*)((const __half*)resv + (size_t)r * N + c));
                    *(__half2*)((__half*)outv + (size_t)r * N + c) =
                        __floats2half2_rn(v0 + rf.x, v1 + rf.y);
                } else if (MODE == 4) {
                    *(__half2*)((__half*)outv + (size_t)r * N + c) =
                        __floats2half2_rn(v0, v1);
                } else {
                    float2 rf = __half22float2(
                        *(const __half2*)((const __half*)resv + (size_t)r * N + c));
                    v0 += rf.x; v1 += rf.y;
                    float* out = (float*)outv;
                    int wi = r >> 4, tt = r & 15;
                    int bb2 = wi >> 6, wh = (wi >> 3) & 7, ww = wi & 7;
                    int hh = wh * 4 + (tt >> 2), wc = ww * 4 + (tt & 3);
                    out[(((size_t)bb2 * C_ + c)     * H_ + hh) * W_ + wc] = v0;
                    out[(((size_t)bb2 * C_ + c + 1) * H_ + hh) * W_ + wc] = v1;
                }
            }
        }
    }
}

// ===================================================================
// Kernel 1: transpose [B,C,H,W] -> token rows (window-major), LN1
// ===================================================================
__global__ void __launch_bounds__(256) ln1_kernel(
    const float* __restrict__ x, const float* __restrict__ nw,
    const float* __restrict__ nb, __half* __restrict__ xh, __half* __restrict__ xn)
{
    extern __shared__ float tile[];  // [32][513]
    __shared__ float s_sum[32], s_sq[32], s_mean[32], s_rstd[32];
    int bidx = blockIdx.x;
    int bb = bidx >> 5, h = bidx & 31;
    int t = threadIdx.x;
    if (t < 32) { s_sum[t] = 0.f; s_sq[t] = 0.f; }
    __syncthreads();

    const float* xp = x + ((size_t)bb * C_) * (H_ * W_) + (size_t)h * W_;
    float lsum = 0.f, lsq = 0.f;
    for (int idx = t; idx < C_ * 32; idx += 256) {
        int c = idx >> 5, ww = idx & 31;
        float v = xp[(size_t)c * (H_ * W_) + ww];
        tile[ww * 513 + c] = v;
        lsum += v; lsq += v * v;
    }
    atomicAdd(&s_sum[t & 31], lsum);
    atomicAdd(&s_sq [t & 31], lsq);
    __syncthreads();
    if (t < 32) {
        float m = s_sum[t] * (1.f / C_);
        float v = s_sq[t] * (1.f / C_) - m * m;
        s_mean[t] = m; s_rstd[t] = rsqrtf(v + EPS_);
    }
    __syncthreads();

    int wh = h >> 2, i = h & 3;
    for (int idx = t; idx < 32 * C_; idx += 256) {
        int ww = idx >> 9, c = idx & (C_ - 1);
        int wwi = ww >> 2, j = ww & 3;
        int wid = (bb * 8 + wh) * 8 + wwi;
        size_t r = (size_t)wid * NTOK + i * 4 + j;
        float v = tile[ww * 513 + c];
        xh[r * C_ + c] = __float2half(v);
        xn[r * C_ + c] = __float2half((v - s_mean[ww]) * s_rstd[ww] * nw[c] + nb[c]);
    }
}

// ===================================================================
// MMA windowed attention, pipelined: block = 4 windows, 256 threads
// (8 warps, 2 heads/warp), double-buffered cp.async staging.
// ===================================================================
#define AROW 1544
#define ABUF (NTOK * AROW)               // halves per buffer
#define WPB  4
#define ATTN_SMEM (2 * ABUF * 2)         // 98816 B

__global__ void __launch_bounds__(256) attn_kernel(
    const __half* __restrict__ qkv, const float* __restrict__ rpb,
    __half* __restrict__ ctx)
{
    extern __shared__ __half skv[];
    const int tid  = threadIdx.x;
    const int lane = tid & 31;
    const int warp = tid >> 5;
    const int tq   = lane & 3, g = lane >> 2;
    const int lsub = lane & 7, sel = lane >> 3;
    const float scale = 0.17677669529663687f;
    const int w0 = blockIdx.x * WPB;

    // staging: 16 threads per row, 12 uint4 chunks each
    const int rr = tid >> 4, cb = tid & 15;

    auto stage = [&](int buf, int w) {
        const __half* src = qkv + ((size_t)(w * NTOK + rr)) * (3 * C_);
        __half* dst = skv + buf * ABUF + rr * AROW;
        #pragma unroll
        for (int j = 0; j < 12; ++j) {
            int c = cb + j * 16;
            cp16(dst + c * 8, src + c * 8);
        }
        CP_COMMIT();
    };

    const uint32_t sb = (uint32_t)__cvta_generic_to_shared(skv);
    const uint32_t ldrow = (uint32_t)(((sel & 1) * 8 + lsub) * (AROW * 2));
    const uint32_t kadd  = (uint32_t)((sel >> 1) * 16);

    auto mkr = [&](int r, int m) {
        return (((r >> 2) - (m >> 2) + 3) * 7 + ((r & 3) - (m & 3) + 3)) * NH_;
    };
    const int m0 = 2 * tq, m1 = 2 * tq + 1, m2 = 2 * tq + 8, m3 = 2 * tq + 9;
    const int bA0 = mkr(g, m0),     bA1 = mkr(g, m1);
    const int bA2 = mkr(g + 8, m0), bA3 = mkr(g + 8, m1);
    const int bB0 = mkr(g, m2),     bB1 = mkr(g, m3);
    const int bB2 = mkr(g + 8, m2), bB3 = mkr(g + 8, m3);

    stage(0, w0);

    #pragma unroll 1
    for (int i = 0; i < WPB; ++i) {
        if (i > 0) __syncthreads();          // compute(i-1) done before overwriting
        if (i < WPB - 1) { stage((i + 1) & 1, w0 + i + 1); CP_WAIT1(); }
        else             { CP_WAIT0(); }
        __syncthreads();

        const int w = w0 + i;
        const uint32_t bufb = sb + (uint32_t)((i & 1) * ABUF * 2);

        #pragma unroll
        for (int hi = 0; hi < 2; ++hi) {
            const int head = warp * 2 + hi;
            const uint32_t hb = (uint32_t)(head * HD_ * 2);

            float sc0[4] = {0.f, 0.f, 0.f, 0.f};
            float sc1[4] = {0.f, 0.f, 0.f, 0.f};
            #pragma unroll
            for (int kc = 0; kc < 2; ++kc) {
                uint32_t aq[4], bk[4];
                LDMX4(aq, bufb + ldrow + hb + kc * 32 + kadd);
                LDMX4(bk, bufb + ldrow + 1024 + hb + kc * 32 + kadd);
                uint32_t b0[2] = { bk[0], bk[2] };
                uint32_t b1[2] = { bk[1], bk[3] };
                mma_f16(sc0, aq, b0);
                mma_f16(sc1, aq, b1);
            }

            sc0[0] = sc0[0] * scale + rpb[bA0 + head];
            sc0[1] = sc0[1] * scale + rpb[bA1 + head];
            sc0[2] = sc0[2] * scale + rpb[bA2 + head];
            sc0[3] = sc0[3] * scale + rpb[bA3 + head];
            sc1[0] = sc1[0] * scale + rpb[bB0 + head];
            sc1[1] = sc1[1] * scale + rpb[bB1 + head];
            sc1[2] = sc1[2] * scale + rpb[bB2 + head];
            sc1[3] = sc1[3] * scale + rpb[bB3 + head];

            float mx0 = fmaxf(fmaxf(sc0[0], sc0[1]), fmaxf(sc1[0], sc1[1]));
            float mx1 = fmaxf(fmaxf(sc0[2], sc0[3]), fmaxf(sc1[2], sc1[3]));
            mx0 = fmaxf(mx0, __shfl_xor_sync(0xffffffffu, mx0, 1));
            mx0 = fmaxf(mx0, __shfl_xor_sync(0xffffffffu, mx0, 2));
            mx1 = fmaxf(mx1, __shfl_xor_sync(0xffffffffu, mx1, 1));
            mx1 = fmaxf(mx1, __shfl_xor_sync(0xffffffffu, mx1, 2));
            sc0[0] = expf(sc0[0] - mx0); sc0[1] = expf(sc0[1] - mx0);
            sc1[0] = expf(sc1[0] - mx0); sc1[1] = expf(sc1[1] - mx0);
            sc0[2] = expf(sc0[2] - mx1); sc0[3] = expf(sc0[3] - mx1);
            sc1[2] = expf(sc1[2] - mx1); sc1[3] = expf(sc1[3] - mx1);
            float sm0 = sc0[0] + sc0[1] + sc1[0] + sc1[1];
            float sm1 = sc0[2] + sc0[3] + sc1[2] + sc1[3];
            sm0 += __shfl_xor_sync(0xffffffffu, sm0, 1);
            sm0 += __shfl_xor_sync(0xffffffffu, sm0, 2);
            sm1 += __shfl_xor_sync(0xffffffffu, sm1, 1);
            sm1 += __shfl_xor_sync(0xffffffffu, sm1, 2);
            float inv0 = 1.f / sm0, inv1 = 1.f / sm1;

            uint32_t pa[4];
            pa[0] = h2u(__floats2half2_rn(sc0[0] * inv0, sc0[1] * inv0));
            pa[1] = h2u(__floats2half2_rn(sc0[2] * inv1, sc0[3] * inv1));
            pa[2] = h2u(__floats2half2_rn(sc1[0] * inv0, sc1[1] * inv0));
            pa[3] = h2u(__floats2half2_rn(sc1[2] * inv1, sc1[3] * inv1));

            uint32_t v0[4], v1[4];
            LDMX4T(v0, bufb + ldrow + 2048 + hb + kadd);
            LDMX4T(v1, bufb + ldrow + 2048 + hb + 32 + kadd);
            float oc[4][4];
            #pragma unroll
            for (int t2 = 0; t2 < 4; ++t2)
                #pragma unroll
                for (int e = 0; e < 4; ++e) oc[t2][e] = 0.f;
            { uint32_t b[2] = { v0[0], v0[1] }; mma_f16(oc[0], pa, b); }
            { uint32_t b[2] = { v0[2], v0[3] }; mma_f16(oc[1], pa, b); }
            { uint32_t b[2] = { v1[0], v1[1] }; mma_f16(oc[2], pa, b); }
            { uint32_t b[2] = { v1[2], v1[3] }; mma_f16(oc[3], pa, b); }

            __half2* o0 = (__half2*)(ctx + (size_t)(w * NTOK + g)     * C_ + head * HD_);
            __half2* o1 = (__half2*)(ctx + (size_t)(w * NTOK + g + 8) * C_ + head * HD_);
            #pragma unroll
            for (int t2 = 0; t2 < 4; ++t2) {
                o0[t2 * 4 + tq] = __floats2half2_rn(oc[t2][0], oc[t2][1]);
                o1[t2 * 4 + tq] = __floats2half2_rn(oc[t2][2], oc[t2][3]);
            }
        }
    }
}

// ===================================================================
// LN2: fp16 in, fp16 out
// ===================================================================
__global__ void __launch_bounds__(128) ln2_kernel(
    const __half* __restrict__ in, const float* __restrict__ nw,
    const float* __restrict__ nb, __half* __restrict__ outp)
{
    int r = blockIdx.x;
    int t = threadIdx.x;
    int lane = t & 31, warp = t >> 5;
    const __half2* ip = (const __half2*)(in + (size_t)r * C_ + t * 4);
    float2 a = __half22float2(ip[0]);
    float2 b = __half22float2(ip[1]);
    float ls = a.x + a.y + b.x + b.y;
    float lq = a.x*a.x + a.y*a.y + b.x*b.x + b.y*b.y;
    #pragma unroll
    for (int off = 16; off; off >>= 1) {
        ls += __shfl_down_sync(0xffffffffu, ls, off);
        lq += __shfl_down_sync(0xffffffffu, lq, off);
    }
    __shared__ float ss[4], sq2[4];
    __shared__ float sm, sr;
    if (lane == 0) { ss[warp] = ls; sq2[warp] = lq; }
    __syncthreads();
    if (t == 0) {
        float S = ss[0] + ss[1] + ss[2] + ss[3];
        float Q = sq2[0] + sq2[1] + sq2[2] + sq2[3];
        float m = S * (1.f / C_);
        float var = Q * (1.f / C_) - m * m;
        sm = m; sr = rsqrtf(var + EPS_);
    }
    __syncthreads();
    float m = sm, rs = sr;
    float4 wv = ((const float4*)nw)[t];
    float4 bv = ((const float4*)nb)[t];
    float o0 = (a.x - m) * rs * wv.x + bv.x;
    float o1 = (a.y - m) * rs * wv.y + bv.y;
    float o2 = (b.x - m) * rs * wv.z + bv.z;
    float o3 = (b.y - m) * rs * wv.w + bv.w;
    __half2* op = (__half2*)(outp + (size_t)r * C_ + t * 4);
    op[0] = __floats2half2_rn(o0, o1);
    op[1] = __floats2half2_rn(o2, o3);
}

// ===================================================================
// host: tensormap creation via driver entry point
// ===================================================================
typedef CUresult (*PFN_encodeTiled)(
    CUtensorMap*, CUtensorMapDataType, cuuint32_t, void*,
    const cuuint64_t*, const cuuint64_t*, const cuuint32_t*, const cuuint32_t*,
    CUtensorMapInterleave, CUtensorMapSwizzle, CUtensorMapL2promotion,
    CUtensorMapFloatOOBfill);

static PFN_encodeTiled get_encoder() {
    static PFN_encodeTiled fn = nullptr;
    if (!fn) {
        void* p = nullptr;
        cudaDriverEntryPointQueryResult qr;
        cudaGetDriverEntryPointByVersion("cuTensorMapEncodeTiled", &p, 12000,
                                         cudaEnableDefault, &qr);
        fn = (PFN_encodeTiled)p;
    }
    return fn;
}

static void make_tm(CUtensorMap* tm, const void* ptr, uint64_t K, uint64_t Rows) {
    cuuint64_t dims[2]    = { K, Rows };
    cuuint64_t strides[1] = { K * 2 };
    cuuint32_t box[2]     = { 64, 128 };
    cuuint32_t es[2]      = { 1, 1 };
    get_encoder()(tm, CU_TENSOR_MAP_DATA_TYPE_UINT16, 2, (void*)ptr,
                  dims, strides, box, es,
                  CU_TENSOR_MAP_INTERLEAVE_NONE, CU_TENSOR_MAP_SWIZZLE_128B,
                  CU_TENSOR_MAP_L2_PROMOTION_L2_128B,
                  CU_TENSOR_MAP_FLOAT_OOB_FILL_NONE);
}

extern "C" void kernel_launch(void* const* d_in, const int* in_sizes, int n_in,
                              void* d_out, int out_size)
{
    const float* x     = (const float*)d_in[0];
    const float* n1w   = (const float*)d_in[1];
    const float* n1b   = (const float*)d_in[2];
    const float* qkvw  = (const float*)d_in[3];
    const float* qkvb  = (const float*)d_in[4];
    const float* rpb   = (const float*)d_in[5];
    const float* projw = (const float*)d_in[6];
    const float* projb = (const float*)d_in[7];
    const float* n2w   = (const float*)d_in[8];
    const float* n2b   = (const float*)d_in[9];
    const float* w1    = (const float*)d_in[10];
    const float* b1    = (const float*)d_in[11];
    const float* w2    = (const float*)d_in[12];
    const float* b2    = (const float*)d_in[13];
    float* out = (float*)d_out;

    __half *xh_h, *xh2_h, *qkv_h, *xn_h, *ctx_h, *hn_h, *h1_h, *wq_h, *wp_h, *w1_h, *w2_h;
    cudaGetSymbolAddress((void**)&xh_h,  g_xh_h);
    cudaGetSymbolAddress((void**)&xh2_h, g_xh2_h);
    cudaGetSymbolAddress((void**)&qkv_h, g_qkv_h);
    cudaGetSymbolAddress((void**)&xn_h,  g_xn_h);
    cudaGetSymbolAddress((void**)&ctx_h, g_ctx_h);
    cudaGetSymbolAddress((void**)&hn_h,  g_hn_h);
    cudaGetSymbolAddress((void**)&h1_h,  g_h1_h);
    cudaGetSymbolAddress((void**)&wq_h,  g_wq_h);
    cudaGetSymbolAddress((void**)&wp_h,  g_wp_h);
    cudaGetSymbolAddress((void**)&w1_h,  g_w1_h);
    cudaGetSymbolAddress((void**)&w2_h,  g_w2_h);

    static CUtensorMap tmA_xn, tmB_wq, tmA_ctx, tmB_wp, tmA_hn, tmB_w1, tmA_h1, tmB_w2;
    make_tm(&tmA_xn,  xn_h,  C_,   T_);
    make_tm(&tmB_wq,  wq_h,  C_,   3 * C_);
    make_tm(&tmA_ctx, ctx_h, C_,   T_);
    make_tm(&tmB_wp,  wp_h,  C_,   C_);
    make_tm(&tmA_hn,  hn_h,  C_,   T_);
    make_tm(&tmB_w1,  w1_h,  C_,   MLPH);
    make_tm(&tmA_h1,  h1_h,  MLPH, T_);
    make_tm(&tmB_w2,  w2_h,  MLPH, C_);

    int ln1_smem = 32 * 513 * 4;
    cudaFuncSetAttribute(ln1_kernel,  cudaFuncAttributeMaxDynamicSharedMemorySize, ln1_smem);
    cudaFuncSetAttribute(attn_kernel, cudaFuncAttributeMaxDynamicSharedMemorySize, ATTN_SMEM);
    cudaFuncSetAttribute(gemm_h<1>, cudaFuncAttributeMaxDynamicSharedMemorySize, GSMEM);
    cudaFuncSetAttribute(gemm_h<2>, cudaFuncAttributeMaxDynamicSharedMemorySize, GSMEM);
    cudaFuncSetAttribute(gemm_h<3>, cudaFuncAttributeMaxDynamicSharedMemorySize, GSMEM);
    cudaFuncSetAttribute(gemm_h<4>, cudaFuncAttributeMaxDynamicSharedMemorySize, GSMEM);

    // 1. transpose + LN1 (fp16 residual + fp16 LN out)
    ln1_kernel<<<B_ * H_, 256, ln1_smem>>>(x, n1w, n1b, xh_h, xn_h);

    // 0. fused weight conversion fp32 -> fp16 (one launch)
    {
        int total = (NQ + NP + N1 + N2) / 4;
        f2h_all_kernel<<<(total + 255) / 256, 256>>>(qkvw, projw, w1, w2,
                                                     wq_h, wp_h, w1_h, w2_h);
    }

    // 2. QKV projection -> fp16 qkv
    gemm_h<4><<<dim3((3 * C_) / 128, T_ / 128), 128, GSMEM>>>(
        tmA_xn, tmB_wq, qkvb, nullptr, qkv_h, 3 * C_, C_);

    // 3. window attention -> fp16 ctx (pipelined 4 windows/block, 256 thr)
    attn_kernel<<<T_ / NTOK / WPB, 256, ATTN_SMEM>>>(qkv_h, rpb, ctx_h);

    // 4. proj + bias + fp16 residual -> fp16 xh2
    gemm_h<2><<<dim3(C_ / 128, T_ / 128), 128, GSMEM>>>(
        tmA_ctx, tmB_wp, projb, xh_h, xh2_h, C_, C_);

    // 5. LN2 (fp16 in) -> fp16 hn
    ln2_kernel<<<T_, 128>>>(xh2_h, n2w, n2b, hn_h);

    // 6. MLP1 + bias + GELU -> fp16 h1
    gemm_h<1><<<dim3(MLPH / 128, T_ / 128), 128, GSMEM>>>(
        tmA_hn, tmB_w1, b1, nullptr, h1_h, MLPH, C_);

    // 7. MLP2 + bias + fp16 residual -> fp32 permuted [B,C,H,W]
    gemm_h<3><<<dim3(C_ / 128, T_ / 128), 128, GSMEM>>>(
        tmA_h1, tmB_w2, b2, xh2_h, out, C_, MLPH);
}